// round 16
// baseline (speedup 1.0000x reference)
#include <cuda_runtime.h>
#include <math.h>
#include <stdint.h>

#define CC   192
#define C3   576
#define NB   2
#define NHD  4
#define HD   48
#define HH   256
#define WW   256
#define HWN  65536

// Scratch (device globals — allocation-free rule)
__device__ float g_qkv1[(size_t)NB * C3 * HWN];     // after 1x1 qkv conv
__device__ float g_qkv2[(size_t)NB * C3 * HWN];     // after dwconv (v only now)
__device__ float g_gram[NB * NHD * HD * HD];        // raw q.k^T accumulators
__device__ float g_attn[NB * NHD * HD * HD];        // softmaxed attention
__device__ float g_sumsq[NB * 2 * CC];              // sum-of-squares q, then k
__device__ float g_m2[NB * CC * CC];                // proj_w @ blockdiag(attn)

// ---------------------------------------------------------------------------
__global__ void zero_kernel() {
    int i = blockIdx.x * blockDim.x + threadIdx.x;
    if (i < NB * NHD * HD * HD) g_gram[i] = 0.f;
    if (i < NB * 2 * CC)        g_sumsq[i] = 0.f;
}

// ---------------------------------------------------------------------------
__device__ __forceinline__ uint32_t f2tf32(float f) {
    uint32_t u;
    asm("cvt.rna.tf32.f32 %0, %1;" : "=r"(u) : "f"(f));
    return u;
}

__device__ __forceinline__ void mma_tf32(float* c, const uint32_t* a, const uint32_t* b) {
    asm volatile(
        "mma.sync.aligned.m16n8k8.row.col.f32.tf32.tf32.f32 "
        "{%0,%1,%2,%3}, {%4,%5,%6,%7}, {%8,%9}, {%0,%1,%2,%3};"
        : "+f"(c[0]), "+f"(c[1]), "+f"(c[2]), "+f"(c[3])
        : "r"(a[0]), "r"(a[1]), "r"(a[2]), "r"(a[3]), "r"(b[0]), "r"(b[1]));
}

// ---------------------------------------------------------------------------
// TF32 tensor-core GEMM (R12 proven config): block 128x128, BK=16, 8 warps,
// warp tile 32x64, occ 2. Compile-time K for full kt unroll.
#define TBM 128
#define TBN 128
#define TBK 16
#define ASTR 20
#define BSTR 136

template<int KC>
__global__ void __launch_bounds__(256, 2)
tf32_gemm(const float* __restrict__ A, const float* __restrict__ B,
          float* __restrict__ C, int M, int N,
          size_t strideA, size_t strideB, size_t strideC) {
    const float* Ap = A + (size_t)blockIdx.z * strideA;
    const float* Bp = B + (size_t)blockIdx.z * strideB;
    float*       Cp = C + (size_t)blockIdx.z * strideC;

    __shared__ uint32_t As[2][TBM * ASTR];
    __shared__ uint32_t Bs[2][TBK * BSTR];

    int tid = threadIdx.x, lane = tid & 31, warp = tid >> 5;
    int wm = warp >> 1, wn = warp & 1;
    int mBase = blockIdx.y * TBM, nBase = blockIdx.x * TBN;

    float4 aReg[2], bReg[2];

    auto ldg = [&](int k0) {
        #pragma unroll
        for (int s = 0; s < 2; s++) {
            int j = tid + 256 * s;
            int row = j >> 2, kc = (j & 3) << 2;
            int gr = mBase + row;
            if (gr < M) aReg[s] = *(const float4*)(Ap + (size_t)gr * KC + k0 + kc);
            else        aReg[s] = make_float4(0.f, 0.f, 0.f, 0.f);
            int kk = j >> 5, n4 = (j & 31) << 2;
            bReg[s] = *(const float4*)(Bp + (size_t)(k0 + kk) * N + nBase + n4);
        }
    };
    auto sts = [&](int buf) {
        #pragma unroll
        for (int s = 0; s < 2; s++) {
            int j = tid + 256 * s;
            int row = j >> 2, kc = (j & 3) << 2;
            uint32_t* p = &As[buf][row * ASTR + kc];
            p[0] = f2tf32(aReg[s].x); p[1] = f2tf32(aReg[s].y);
            p[2] = f2tf32(aReg[s].z); p[3] = f2tf32(aReg[s].w);
            int kk = j >> 5, n4 = (j & 31) << 2;
            uint32_t* q = &Bs[buf][kk * BSTR + n4];
            q[0] = f2tf32(bReg[s].x); q[1] = f2tf32(bReg[s].y);
            q[2] = f2tf32(bReg[s].z); q[3] = f2tf32(bReg[s].w);
        }
    };

    float acc[2][8][4] = {};

    auto compute = [&](int buf) {
        #pragma unroll
        for (int k8 = 0; k8 < 2; k8++) {
            uint32_t a[2][4], b[8][2];
            #pragma unroll
            for (int mi = 0; mi < 2; mi++) {
                int r = wm * 32 + mi * 16 + (lane >> 2);
                int c = k8 * 8 + (lane & 3);
                a[mi][0] = As[buf][r * ASTR + c];
                a[mi][1] = As[buf][(r + 8) * ASTR + c];
                a[mi][2] = As[buf][r * ASTR + c + 4];
                a[mi][3] = As[buf][(r + 8) * ASTR + c + 4];
            }
            #pragma unroll
            for (int ni = 0; ni < 8; ni++) {
                int kk = k8 * 8 + (lane & 3);
                int n = wn * 64 + ni * 8 + (lane >> 2);
                b[ni][0] = Bs[buf][kk * BSTR + n];
                b[ni][1] = Bs[buf][(kk + 4) * BSTR + n];
            }
            #pragma unroll
            for (int mi = 0; mi < 2; mi++)
                #pragma unroll
                for (int ni = 0; ni < 8; ni++)
                    mma_tf32(acc[mi][ni], a[mi], b[ni]);
        }
    };

    constexpr int nk = KC / TBK;
    ldg(0);
    sts(0);
    __syncthreads();
    #pragma unroll
    for (int kt = 0; kt < nk; kt++) {
        if (kt + 1 < nk) ldg((kt + 1) * TBK);
        compute(kt & 1);
        if (kt + 1 < nk) sts((kt + 1) & 1);
        __syncthreads();
    }

    #pragma unroll
    for (int mi = 0; mi < 2; mi++) {
        int r0 = mBase + wm * 32 + mi * 16 + (lane >> 2);
        #pragma unroll
        for (int ni = 0; ni < 8; ni++) {
            int col = nBase + wn * 64 + ni * 8 + (lane & 3) * 2;
            if (r0 < M)
                *(float2*)(Cp + (size_t)r0 * N + col) =
                    make_float2(acc[mi][ni][0], acc[mi][ni][1]);
            if (r0 + 8 < M)
                *(float2*)(Cp + (size_t)(r0 + 8) * N + col) =
                    make_float2(acc[mi][ni][2], acc[mi][ni][3]);
        }
    }
}

// ---------------------------------------------------------------------------
// Depthwise 3x3, pad 1 (cross-correlation). 4x4 output strip per thread.
// Used for the v channels only.
__global__ void dwconv_kernel(const float* __restrict__ w, int chOff, int nch) {
    size_t t = (size_t)blockIdx.x * blockDim.x + threadIdx.x;
    int x4 = (int)(t & 63) * 4;
    int y4 = (int)((t >> 6) & 63) * 4;
    int idx = (int)(t >> 12);
    if (idx >= NB * nch) return;
    int b  = idx / nch;
    int ch = chOff + idx % nch;
    size_t plane = (size_t)b * C3 + ch;
    const float* in = g_qkv1 + plane * HWN;
    const float* wp = w + ch * 9;
    float w00 = wp[0], w01 = wp[1], w02 = wp[2];
    float w10 = wp[3], w11 = wp[4], w12 = wp[5];
    float w20 = wp[6], w21 = wp[7], w22 = wp[8];

    float4 rC[6];
    float  rL[6], rR[6];
    #pragma unroll
    for (int j = 0; j < 6; j++) {
        int yy = y4 - 1 + j;
        if (yy < 0 || yy >= HH) {
            rC[j] = make_float4(0.f, 0.f, 0.f, 0.f);
            rL[j] = 0.f; rR[j] = 0.f;
        } else {
            const float* rp = in + yy * WW + x4;
            rC[j] = *(const float4*)rp;
            rL[j] = (x4 > 0)      ? rp[-1] : 0.f;
            rR[j] = (x4 + 4 < WW) ? rp[4]  : 0.f;
        }
    }

    float* outp = g_qkv2 + plane * HWN + y4 * WW + x4;
    #pragma unroll
    for (int i = 0; i < 4; i++) {
        float4 o;
        o.x = w00 * rL[i]     + w01 * rC[i].x   + w02 * rC[i].y
            + w10 * rL[i + 1] + w11 * rC[i + 1].x + w12 * rC[i + 1].y
            + w20 * rL[i + 2] + w21 * rC[i + 2].x + w22 * rC[i + 2].y;
        o.y = w00 * rC[i].x   + w01 * rC[i].y   + w02 * rC[i].z
            + w10 * rC[i + 1].x + w11 * rC[i + 1].y + w12 * rC[i + 1].z
            + w20 * rC[i + 2].x + w21 * rC[i + 2].y + w22 * rC[i + 2].z;
        o.z = w00 * rC[i].y   + w01 * rC[i].z   + w02 * rC[i].w
            + w10 * rC[i + 1].y + w11 * rC[i + 1].z + w12 * rC[i + 1].w
            + w20 * rC[i + 2].y + w21 * rC[i + 2].z + w22 * rC[i + 2].w;
        o.w = w00 * rC[i].z   + w01 * rC[i].w   + w02 * rR[i]
            + w10 * rC[i + 1].z + w11 * rC[i + 1].w + w12 * rR[i + 1]
            + w20 * rC[i + 2].z + w21 * rC[i + 2].w + w22 * rR[i + 2];
        *(float4*)(outp + i * WW) = o;
    }
}

// ---------------------------------------------------------------------------
// FUSED: dwconv(q,k) computed inline from g_qkv1 + tensor-core gram + sumsq.
// q,k dwconv outputs are never materialized to global memory.
// Span = 2 image rows (512 spatial); chunk = 64 spatial within one row.
#define GSPL 128
#define GCH  64
#define QSTR 68

// dwconv for 4 outputs at (y, gx..gx+3), weights w[9], input plane.
__device__ __forceinline__ void conv4(const float* __restrict__ in,
                                      const float* __restrict__ wp,
                                      int y, int gx, float4& o) {
    o = make_float4(0.f, 0.f, 0.f, 0.f);
    #pragma unroll
    for (int dy = 0; dy < 3; dy++) {
        int yy = y + dy - 1;
        if (yy < 0 || yy >= HH) continue;
        const float* rp = in + yy * WW + gx;
        float4 c = *(const float4*)rp;
        float left  = (gx > 0)      ? rp[-1] : 0.f;
        float right = (gx + 4 < WW) ? rp[4]  : 0.f;
        float w0 = wp[dy * 3], w1 = wp[dy * 3 + 1], w2 = wp[dy * 3 + 2];
        o.x += w0 * left + w1 * c.x + w2 * c.y;
        o.y += w0 * c.x  + w1 * c.y + w2 * c.z;
        o.z += w0 * c.y  + w1 * c.z + w2 * c.w;
        o.w += w0 * c.z  + w1 * c.w + w2 * right;
    }
}

__global__ void __launch_bounds__(192)
gram_kernel(const float* __restrict__ w) {
    int bh = blockIdx.y;
    int b = bh >> 2, h = bh & 3;

    __shared__ uint32_t qs[HD * QSTR];
    __shared__ uint32_t ks[HD * QSTR];

    int tid = threadIdx.x, lane = tid & 31, warp = tid >> 5;
    int c_own = tid >> 2;      // channel within head (0..47)
    int sg    = tid & 3;       // quad slot
    int n0 = warp * 8;
    float acc[3][4] = {};
    float ssq = 0.f, ssk = 0.f;

    const float* qin = g_qkv1 + ((size_t)b * C3 + h * HD + c_own) * HWN;
    const float* kin = g_qkv1 + ((size_t)b * C3 + CC + h * HD + c_own) * HWN;
    const float* wq = w + (h * HD + c_own) * 9;
    const float* wk = w + (CC + h * HD + c_own) * 9;

    int ybase = blockIdx.y >= 0 ? blockIdx.x * 2 : 0;   // 2 rows per span

    #pragma unroll 1
    for (int cs = 0; cs < 8; cs++) {
        int y  = ybase + (cs >> 2);
        int x0 = (cs & 3) * 64;
        // fill: compute conv outputs for this chunk, 16 values per thread
        #pragma unroll
        for (int j = 0; j < 4; j++) {
            int gx = x0 + j * 16 + sg * 4;
            float4 qo, ko;
            conv4(qin, wq, y, gx, qo);
            conv4(kin, wk, y, gx, ko);
            ssq += qo.x * qo.x + qo.y * qo.y + qo.z * qo.z + qo.w * qo.w;
            ssk += ko.x * ko.x + ko.y * ko.y + ko.z * ko.z + ko.w * ko.w;
            int s = j * 16 + sg * 4;
            uint4 qt = make_uint4(f2tf32(qo.x), f2tf32(qo.y),
                                  f2tf32(qo.z), f2tf32(qo.w));
            uint4 kt = make_uint4(f2tf32(ko.x), f2tf32(ko.y),
                                  f2tf32(ko.z), f2tf32(ko.w));
            *(uint4*)&qs[c_own * QSTR + s] = qt;
            *(uint4*)&ks[c_own * QSTR + s] = kt;
        }
        __syncthreads();
        #pragma unroll
        for (int k8 = 0; k8 < GCH / 8; k8++) {
            int k0 = k8 * 8 + (lane & 3);
            uint32_t bf[2];
            int brow = n0 + (lane >> 2);
            bf[0] = ks[brow * QSTR + k0];
            bf[1] = ks[brow * QSTR + k0 + 4];
            #pragma unroll
            for (int mi = 0; mi < 3; mi++) {
                int ar = mi * 16 + (lane >> 2);
                uint32_t af[4];
                af[0] = qs[ar * QSTR + k0];
                af[1] = qs[(ar + 8) * QSTR + k0];
                af[2] = qs[ar * QSTR + k0 + 4];
                af[3] = qs[(ar + 8) * QSTR + k0 + 4];
                mma_tf32(acc[mi], af, bf);
            }
        }
        __syncthreads();
    }

    float* gp = g_gram + (size_t)bh * HD * HD;
    int col = n0 + (lane & 3) * 2;
    #pragma unroll
    for (int mi = 0; mi < 3; mi++) {
        int r = mi * 16 + (lane >> 2);
        atomicAdd(&gp[r * HD + col],           acc[mi][0]);
        atomicAdd(&gp[r * HD + col + 1],       acc[mi][1]);
        atomicAdd(&gp[(r + 8) * HD + col],     acc[mi][2]);
        atomicAdd(&gp[(r + 8) * HD + col + 1], acc[mi][3]);
    }

    ssq += __shfl_xor_sync(0xffffffffu, ssq, 1);
    ssq += __shfl_xor_sync(0xffffffffu, ssq, 2);
    ssk += __shfl_xor_sync(0xffffffffu, ssk, 1);
    ssk += __shfl_xor_sync(0xffffffffu, ssk, 2);
    if (sg == 0) {
        atomicAdd(&g_sumsq[b * 2 * CC + h * HD + c_own], ssq);
        atomicAdd(&g_sumsq[b * 2 * CC + CC + h * HD + c_own], ssk);
    }
}

// ---------------------------------------------------------------------------
__global__ void attn_kernel(const float* __restrict__ temp) {
    int r = blockIdx.x * blockDim.x + threadIdx.x;
    if (r >= NB * NHD * HD) return;
    int b = r / (NHD * HD);
    int h = (r / HD) % NHD;
    int c = r % HD;
    float nq = fmaxf(sqrtf(g_sumsq[b * 2 * CC + h * HD + c]), 1e-12f);
    const float* gr = g_gram + (size_t)((b * NHD + h) * HD + c) * HD;
    float t = temp[h];
    float a[HD];
    float mx = -1e30f;
    for (int d = 0; d < HD; d++) {
        float nk = fmaxf(sqrtf(g_sumsq[b * 2 * CC + CC + h * HD + d]), 1e-12f);
        float v = gr[d] / (nq * nk) * t;
        a[d] = v;
        mx = fmaxf(mx, v);
    }
    float sum = 0.f;
    for (int d = 0; d < HD; d++) { a[d] = expf(a[d] - mx); sum += a[d]; }
    float inv = 1.f / sum;
    float* o = g_attn + (size_t)((b * NHD + h) * HD + c) * HD;
    for (int d = 0; d < HD; d++) o[d] = a[d] * inv;
}

// ---------------------------------------------------------------------------
// M2[b] = proj_w @ blockdiag(attn[b])
__global__ void m2_kernel(const float* __restrict__ P) {
    int idx = blockIdx.x * blockDim.x + threadIdx.x;
    if (idx >= NB * CC * CC) return;
    int b = idx / (CC * CC);
    int o = (idx / CC) % CC;
    int g = idx % CC;
    int h = g / HD, d = g % HD;
    const float* pr = P + (size_t)o * CC + h * HD;
    const float* at = g_attn + (size_t)((b * NHD + h) * HD) * HD + d;
    float s = 0.f;
    #pragma unroll
    for (int c = 0; c < HD; c++) s += pr[c] * at[c * HD];
    g_m2[idx] = s;
}

// ---------------------------------------------------------------------------
extern "C" void kernel_launch(void* const* d_in, const int* in_sizes, int n_in,
                              void* d_out, int out_size) {
    const float* x      = (const float*)d_in[0];
    const float* qkv_w  = (const float*)d_in[1];
    const float* dw_w   = (const float*)d_in[2];
    const float* proj_w = (const float*)d_in[3];
    const float* temp   = (const float*)d_in[4];
    float* out = (float*)d_out;

    float *qkv1, *qkv2, *m2;
    cudaGetSymbolAddress((void**)&qkv1, g_qkv1);
    cudaGetSymbolAddress((void**)&qkv2, g_qkv2);
    cudaGetSymbolAddress((void**)&m2,   g_m2);

    cudaStream_t s2;
    cudaStreamCreateWithFlags(&s2, cudaStreamNonBlocking);
    cudaEvent_t evA, evB;
    cudaEventCreateWithFlags(&evA, cudaEventDisableTiming);
    cudaEventCreateWithFlags(&evB, cudaEventDisableTiming);

    // ---- default stream: zero + q,k-channel GEMM ----
    zero_kernel<<<(NB * NHD * HD * HD + 255) / 256, 256>>>();

    tf32_gemm<CC><<<dim3(HWN / TBN, 3, NB), 256>>>(
        qkv_w, x, qkv1, 2 * CC, HWN,
        0, (size_t)CC * HWN, (size_t)C3 * HWN);

    cudaEventRecord(evA, 0);

    // ---- s2 branch: fused dwconv(q,k)+gram -> attn -> m2 ----
    cudaStreamWaitEvent(s2, evA, 0);
    gram_kernel<<<dim3(GSPL, NB * NHD), 192, 0, s2>>>(dw_w);
    attn_kernel<<<2, 192, 0, s2>>>(temp);
    m2_kernel<<<(NB * CC * CC + 255) / 256, 256, 0, s2>>>(proj_w);
    cudaEventRecord(evB, s2);

    // ---- default stream: v-channel GEMM + dwconv(v) ----
    tf32_gemm<CC><<<dim3(HWN / TBN, 2, NB), 256>>>(
        qkv_w + (size_t)2 * CC * CC, x, qkv1 + (size_t)2 * CC * HWN, CC, HWN,
        0, (size_t)CC * HWN, (size_t)C3 * HWN);
    dwconv_kernel<<<(int)(((size_t)NB * CC * HWN) / 16 / 256), 256>>>(
        dw_w, 2 * CC, CC);

    cudaStreamWaitEvent(0, evB, 0);

    // final: out[b] = M2[b] @ v[b]
    tf32_gemm<CC><<<dim3(HWN / TBN, (CC + TBM - 1) / TBM, NB), 256>>>(
        m2, qkv2 + (size_t)2 * CC * HWN, out, CC, HWN,
        (size_t)CC * CC, (size_t)C3 * HWN, (size_t)CC * HWN);
}

// round 17
// speedup vs baseline: 1.0811x; 1.0811x over previous
#include <cuda_runtime.h>
#include <math.h>
#include <stdint.h>

#define CC   192
#define C3   576
#define NB   2
#define NHD  4
#define HD   48
#define HH   256
#define WW   256
#define HWN  65536

// Scratch (device globals — allocation-free rule)
__device__ float g_qkv1[(size_t)NB * C3 * HWN];     // after 1x1 qkv conv
__device__ float g_qkv2[(size_t)NB * C3 * HWN];     // after depthwise 3x3
__device__ float g_gram[NB * NHD * HD * HD];        // raw q.k^T accumulators
__device__ float g_attn[NB * NHD * HD * HD];        // softmaxed attention
__device__ float g_sumsq[NB * 2 * CC];              // sum-of-squares q, then k
__device__ float g_m2[NB * CC * CC];                // proj_w @ blockdiag(attn)

// ---------------------------------------------------------------------------
__global__ void zero_kernel() {
    int i = blockIdx.x * blockDim.x + threadIdx.x;
    if (i < NB * NHD * HD * HD) g_gram[i] = 0.f;
    if (i < NB * 2 * CC)        g_sumsq[i] = 0.f;
}

// ---------------------------------------------------------------------------
__device__ __forceinline__ uint32_t f2tf32(float f) {
    uint32_t u;
    asm("cvt.rna.tf32.f32 %0, %1;" : "=r"(u) : "f"(f));
    return u;
}

__device__ __forceinline__ void mma_tf32(float* c, const uint32_t* a, const uint32_t* b) {
    asm volatile(
        "mma.sync.aligned.m16n8k8.row.col.f32.tf32.tf32.f32 "
        "{%0,%1,%2,%3}, {%4,%5,%6,%7}, {%8,%9}, {%0,%1,%2,%3};"
        : "+f"(c[0]), "+f"(c[1]), "+f"(c[2]), "+f"(c[3])
        : "r"(a[0]), "r"(a[1]), "r"(a[2]), "r"(a[3]), "r"(b[0]), "r"(b[1]));
}

// ---------------------------------------------------------------------------
// TF32 tensor-core GEMM (R12 proven config): block 128x128, BK=16, 8 warps,
// warp tile 32x64, occ 2. Compile-time K for full kt unroll.
#define TBM 128
#define TBN 128
#define TBK 16
#define ASTR 20
#define BSTR 136

template<int KC>
__global__ void __launch_bounds__(256, 2)
tf32_gemm(const float* __restrict__ A, const float* __restrict__ B,
          float* __restrict__ C, int M, int N,
          size_t strideA, size_t strideB, size_t strideC) {
    const float* Ap = A + (size_t)blockIdx.z * strideA;
    const float* Bp = B + (size_t)blockIdx.z * strideB;
    float*       Cp = C + (size_t)blockIdx.z * strideC;

    __shared__ uint32_t As[2][TBM * ASTR];
    __shared__ uint32_t Bs[2][TBK * BSTR];

    int tid = threadIdx.x, lane = tid & 31, warp = tid >> 5;
    int wm = warp >> 1, wn = warp & 1;
    int mBase = blockIdx.y * TBM, nBase = blockIdx.x * TBN;

    float4 aReg[2], bReg[2];

    auto ldg = [&](int k0) {
        #pragma unroll
        for (int s = 0; s < 2; s++) {
            int j = tid + 256 * s;
            int row = j >> 2, kc = (j & 3) << 2;
            int gr = mBase + row;
            if (gr < M) aReg[s] = *(const float4*)(Ap + (size_t)gr * KC + k0 + kc);
            else        aReg[s] = make_float4(0.f, 0.f, 0.f, 0.f);
            int kk = j >> 5, n4 = (j & 31) << 2;
            bReg[s] = *(const float4*)(Bp + (size_t)(k0 + kk) * N + nBase + n4);
        }
    };
    auto sts = [&](int buf) {
        #pragma unroll
        for (int s = 0; s < 2; s++) {
            int j = tid + 256 * s;
            int row = j >> 2, kc = (j & 3) << 2;
            uint32_t* p = &As[buf][row * ASTR + kc];
            p[0] = f2tf32(aReg[s].x); p[1] = f2tf32(aReg[s].y);
            p[2] = f2tf32(aReg[s].z); p[3] = f2tf32(aReg[s].w);
            int kk = j >> 5, n4 = (j & 31) << 2;
            uint32_t* q = &Bs[buf][kk * BSTR + n4];
            q[0] = f2tf32(bReg[s].x); q[1] = f2tf32(bReg[s].y);
            q[2] = f2tf32(bReg[s].z); q[3] = f2tf32(bReg[s].w);
        }
    };

    float acc[2][8][4] = {};

    auto compute = [&](int buf) {
        #pragma unroll
        for (int k8 = 0; k8 < 2; k8++) {
            uint32_t a[2][4], b[8][2];
            #pragma unroll
            for (int mi = 0; mi < 2; mi++) {
                int r = wm * 32 + mi * 16 + (lane >> 2);
                int c = k8 * 8 + (lane & 3);
                a[mi][0] = As[buf][r * ASTR + c];
                a[mi][1] = As[buf][(r + 8) * ASTR + c];
                a[mi][2] = As[buf][r * ASTR + c + 4];
                a[mi][3] = As[buf][(r + 8) * ASTR + c + 4];
            }
            #pragma unroll
            for (int ni = 0; ni < 8; ni++) {
                int kk = k8 * 8 + (lane & 3);
                int n = wn * 64 + ni * 8 + (lane >> 2);
                b[ni][0] = Bs[buf][kk * BSTR + n];
                b[ni][1] = Bs[buf][(kk + 4) * BSTR + n];
            }
            #pragma unroll
            for (int mi = 0; mi < 2; mi++)
                #pragma unroll
                for (int ni = 0; ni < 8; ni++)
                    mma_tf32(acc[mi][ni], a[mi], b[ni]);
        }
    };

    constexpr int nk = KC / TBK;
    ldg(0);
    sts(0);
    __syncthreads();
    #pragma unroll
    for (int kt = 0; kt < nk; kt++) {
        if (kt + 1 < nk) ldg((kt + 1) * TBK);
        compute(kt & 1);
        if (kt + 1 < nk) sts((kt + 1) & 1);
        __syncthreads();
    }

    #pragma unroll
    for (int mi = 0; mi < 2; mi++) {
        int r0 = mBase + wm * 32 + mi * 16 + (lane >> 2);
        #pragma unroll
        for (int ni = 0; ni < 8; ni++) {
            int col = nBase + wn * 64 + ni * 8 + (lane & 3) * 2;
            if (r0 < M)
                *(float2*)(Cp + (size_t)r0 * N + col) =
                    make_float2(acc[mi][ni][0], acc[mi][ni][1]);
            if (r0 + 8 < M)
                *(float2*)(Cp + (size_t)(r0 + 8) * N + col) =
                    make_float2(acc[mi][ni][2], acc[mi][ni][3]);
        }
    }
}

// ---------------------------------------------------------------------------
// Depthwise 3x3, pad 1 (cross-correlation). 4x4 output strip per thread.
// Operates on channel range [chOff, chOff+nch) for every batch.
__global__ void dwconv_kernel(const float* __restrict__ w, int chOff, int nch) {
    size_t t = (size_t)blockIdx.x * blockDim.x + threadIdx.x;
    int x4 = (int)(t & 63) * 4;
    int y4 = (int)((t >> 6) & 63) * 4;
    int idx = (int)(t >> 12);
    if (idx >= NB * nch) return;
    int b  = idx / nch;
    int ch = chOff + idx % nch;
    size_t plane = (size_t)b * C3 + ch;
    const float* in = g_qkv1 + plane * HWN;
    const float* wp = w + ch * 9;
    float w00 = wp[0], w01 = wp[1], w02 = wp[2];
    float w10 = wp[3], w11 = wp[4], w12 = wp[5];
    float w20 = wp[6], w21 = wp[7], w22 = wp[8];

    float4 rC[6];
    float  rL[6], rR[6];
    #pragma unroll
    for (int j = 0; j < 6; j++) {
        int yy = y4 - 1 + j;
        if (yy < 0 || yy >= HH) {
            rC[j] = make_float4(0.f, 0.f, 0.f, 0.f);
            rL[j] = 0.f; rR[j] = 0.f;
        } else {
            const float* rp = in + yy * WW + x4;
            rC[j] = *(const float4*)rp;
            rL[j] = (x4 > 0)      ? rp[-1] : 0.f;
            rR[j] = (x4 + 4 < WW) ? rp[4]  : 0.f;
        }
    }

    float* outp = g_qkv2 + plane * HWN + y4 * WW + x4;
    #pragma unroll
    for (int i = 0; i < 4; i++) {
        float4 o;
        o.x = w00 * rL[i]     + w01 * rC[i].x   + w02 * rC[i].y
            + w10 * rL[i + 1] + w11 * rC[i + 1].x + w12 * rC[i + 1].y
            + w20 * rL[i + 2] + w21 * rC[i + 2].x + w22 * rC[i + 2].y;
        o.y = w00 * rC[i].x   + w01 * rC[i].y   + w02 * rC[i].z
            + w10 * rC[i + 1].x + w11 * rC[i + 1].y + w12 * rC[i + 1].z
            + w20 * rC[i + 2].x + w21 * rC[i + 2].y + w22 * rC[i + 2].z;
        o.z = w00 * rC[i].y   + w01 * rC[i].z   + w02 * rC[i].w
            + w10 * rC[i + 1].y + w11 * rC[i + 1].z + w12 * rC[i + 1].w
            + w20 * rC[i + 2].y + w21 * rC[i + 2].z + w22 * rC[i + 2].w;
        o.w = w00 * rC[i].z   + w01 * rC[i].w   + w02 * rR[i]
            + w10 * rC[i + 1].z + w11 * rC[i + 1].w + w12 * rR[i + 1]
            + w20 * rC[i + 2].z + w21 * rC[i + 2].w + w22 * rR[i + 2];
        *(float4*)(outp + i * WW) = o;
    }
}

// ---------------------------------------------------------------------------
// Tensor-core gram + fused per-channel sum-of-squares (R12 proven config).
#define GSPL 128
#define GCH  64
#define QSTR 68
__global__ void __launch_bounds__(192)
gram_kernel() {
    int bh = blockIdx.y;
    int b = bh >> 2, h = bh & 3;
    const float* qb = g_qkv2 + ((size_t)b * C3 + h * HD) * HWN;
    const float* kb = g_qkv2 + ((size_t)b * C3 + CC + h * HD) * HWN;

    __shared__ uint32_t qs[HD * QSTR];
    __shared__ uint32_t ks[HD * QSTR];

    int tid = threadIdx.x, lane = tid & 31, warp = tid >> 5;
    int c_own = tid >> 2;
    int sg    = tid & 3;
    int n0 = warp * 8;
    float acc[3][4] = {};
    float ssq = 0.f, ssk = 0.f;

    int base = blockIdx.x * (HWN / GSPL);
    for (int cs = 0; cs < HWN / GSPL; cs += GCH) {
        int s0 = base + cs;
        const float* qrow = qb + (size_t)c_own * HWN + s0;
        const float* krow = kb + (size_t)c_own * HWN + s0;
        #pragma unroll
        for (int j = 0; j < 4; j++) {
            int s = j * 16 + sg * 4;
            float4 qv = *(const float4*)(qrow + s);
            float4 kv = *(const float4*)(krow + s);
            ssq += qv.x * qv.x + qv.y * qv.y + qv.z * qv.z + qv.w * qv.w;
            ssk += kv.x * kv.x + kv.y * kv.y + kv.z * kv.z + kv.w * kv.w;
            uint4 qt = make_uint4(f2tf32(qv.x), f2tf32(qv.y), f2tf32(qv.z), f2tf32(qv.w));
            uint4 kt = make_uint4(f2tf32(kv.x), f2tf32(kv.y), f2tf32(kv.z), f2tf32(kv.w));
            *(uint4*)&qs[c_own * QSTR + s] = qt;
            *(uint4*)&ks[c_own * QSTR + s] = kt;
        }
        __syncthreads();
        #pragma unroll
        for (int k8 = 0; k8 < GCH / 8; k8++) {
            int k0 = k8 * 8 + (lane & 3);
            uint32_t bf[2];
            int brow = n0 + (lane >> 2);
            bf[0] = ks[brow * QSTR + k0];
            bf[1] = ks[brow * QSTR + k0 + 4];
            #pragma unroll
            for (int mi = 0; mi < 3; mi++) {
                int ar = mi * 16 + (lane >> 2);
                uint32_t af[4];
                af[0] = qs[ar * QSTR + k0];
                af[1] = qs[(ar + 8) * QSTR + k0];
                af[2] = qs[ar * QSTR + k0 + 4];
                af[3] = qs[(ar + 8) * QSTR + k0 + 4];
                mma_tf32(acc[mi], af, bf);
            }
        }
        __syncthreads();
    }

    float* gp = g_gram + (size_t)bh * HD * HD;
    int col = n0 + (lane & 3) * 2;
    #pragma unroll
    for (int mi = 0; mi < 3; mi++) {
        int r = mi * 16 + (lane >> 2);
        atomicAdd(&gp[r * HD + col],           acc[mi][0]);
        atomicAdd(&gp[r * HD + col + 1],       acc[mi][1]);
        atomicAdd(&gp[(r + 8) * HD + col],     acc[mi][2]);
        atomicAdd(&gp[(r + 8) * HD + col + 1], acc[mi][3]);
    }

    ssq += __shfl_xor_sync(0xffffffffu, ssq, 1);
    ssq += __shfl_xor_sync(0xffffffffu, ssq, 2);
    ssk += __shfl_xor_sync(0xffffffffu, ssk, 1);
    ssk += __shfl_xor_sync(0xffffffffu, ssk, 2);
    if (sg == 0) {
        atomicAdd(&g_sumsq[b * 2 * CC + h * HD + c_own], ssq);
        atomicAdd(&g_sumsq[b * 2 * CC + CC + h * HD + c_own], ssk);
    }
}

// ---------------------------------------------------------------------------
// Warp-per-row softmax: 384 rows, 96 blocks x 4 warps.
// lane owns columns lane and lane+32 (lane<16).
__global__ void attn_kernel(const float* __restrict__ temp) {
    int r = blockIdx.x * 4 + (threadIdx.x >> 5);
    int lane = threadIdx.x & 31;
    if (r >= NB * NHD * HD) return;
    int b = r / (NHD * HD);
    int h = (r / HD) % NHD;
    int c = r % HD;
    float nq = fmaxf(sqrtf(g_sumsq[b * 2 * CC + h * HD + c]), 1e-12f);
    const float* gr = g_gram + (size_t)((b * NHD + h) * HD + c) * HD;
    float t = temp[h];

    int d0 = lane, d1 = lane + 32;
    float v0 = -1e30f, v1 = -1e30f;
    {
        float nk = fmaxf(sqrtf(g_sumsq[b * 2 * CC + CC + h * HD + d0]), 1e-12f);
        v0 = gr[d0] / (nq * nk) * t;
    }
    if (d1 < HD) {
        float nk = fmaxf(sqrtf(g_sumsq[b * 2 * CC + CC + h * HD + d1]), 1e-12f);
        v1 = gr[d1] / (nq * nk) * t;
    }
    float mx = fmaxf(v0, v1);
    #pragma unroll
    for (int s = 16; s > 0; s >>= 1)
        mx = fmaxf(mx, __shfl_xor_sync(0xffffffffu, mx, s));

    float e0 = expf(v0 - mx);
    float e1 = (d1 < HD) ? expf(v1 - mx) : 0.f;
    float sum = e0 + e1;
    #pragma unroll
    for (int s = 16; s > 0; s >>= 1)
        sum += __shfl_xor_sync(0xffffffffu, sum, s);

    float inv = 1.f / sum;
    float* o = g_attn + (size_t)((b * NHD + h) * HD + c) * HD;
    o[d0] = e0 * inv;
    if (d1 < HD) o[d1] = e1 * inv;
}

// ---------------------------------------------------------------------------
// M2[b] = proj_w @ blockdiag(attn[b])
__global__ void m2_kernel(const float* __restrict__ P) {
    int idx = blockIdx.x * blockDim.x + threadIdx.x;
    if (idx >= NB * CC * CC) return;
    int b = idx / (CC * CC);
    int o = (idx / CC) % CC;
    int g = idx % CC;
    int h = g / HD, d = g % HD;
    const float* pr = P + (size_t)o * CC + h * HD;
    const float* at = g_attn + (size_t)((b * NHD + h) * HD) * HD + d;
    float s = 0.f;
    #pragma unroll
    for (int c = 0; c < HD; c++) s += pr[c] * at[c * HD];
    g_m2[idx] = s;
}

// ---------------------------------------------------------------------------
extern "C" void kernel_launch(void* const* d_in, const int* in_sizes, int n_in,
                              void* d_out, int out_size) {
    const float* x      = (const float*)d_in[0];
    const float* qkv_w  = (const float*)d_in[1];
    const float* dw_w   = (const float*)d_in[2];
    const float* proj_w = (const float*)d_in[3];
    const float* temp   = (const float*)d_in[4];
    float* out = (float*)d_out;

    float *qkv1, *qkv2, *m2;
    cudaGetSymbolAddress((void**)&qkv1, g_qkv1);
    cudaGetSymbolAddress((void**)&qkv2, g_qkv2);
    cudaGetSymbolAddress((void**)&m2,   g_m2);

    cudaStream_t s2;
    cudaStreamCreateWithFlags(&s2, cudaStreamNonBlocking);
    cudaEvent_t evA, evB;
    cudaEventCreateWithFlags(&evA, cudaEventDisableTiming);
    cudaEventCreateWithFlags(&evB, cudaEventDisableTiming);

    // ---- default stream: zero + q,k-channel GEMM ----
    zero_kernel<<<(NB * NHD * HD * HD + 255) / 256, 256>>>();

    tf32_gemm<CC><<<dim3(HWN / TBN, 3, NB), 256>>>(
        qkv_w, x, qkv1, 2 * CC, HWN,
        0, (size_t)CC * HWN, (size_t)C3 * HWN);

    cudaEventRecord(evA, 0);

    // ---- s2 branch: dwconv(q,k) -> gram -> attn -> m2 ----
    cudaStreamWaitEvent(s2, evA, 0);
    dwconv_kernel<<<(int)(((size_t)NB * 2 * CC * HWN) / 16 / 256), 256, 0, s2>>>(
        dw_w, 0, 2 * CC);
    gram_kernel<<<dim3(GSPL, NB * NHD), 192, 0, s2>>>();
    attn_kernel<<<96, 128, 0, s2>>>(temp);
    m2_kernel<<<(NB * CC * CC + 255) / 256, 256, 0, s2>>>(proj_w);
    cudaEventRecord(evB, s2);

    // ---- default stream: v-channel GEMM + dwconv(v) ----
    tf32_gemm<CC><<<dim3(HWN / TBN, 2, NB), 256>>>(
        qkv_w + (size_t)2 * CC * CC, x, qkv1 + (size_t)2 * CC * HWN, CC, HWN,
        0, (size_t)CC * HWN, (size_t)C3 * HWN);
    dwconv_kernel<<<(int)(((size_t)NB * CC * HWN) / 16 / 256), 256>>>(
        dw_w, 2 * CC, CC);

    cudaStreamWaitEvent(0, evB, 0);

    // final: out[b] = M2[b] @ v[b]
    tf32_gemm<CC><<<dim3(HWN / TBN, (CC + TBM - 1) / TBM, NB), 256>>>(
        m2, qkv2 + (size_t)2 * CC * HWN, out, CC, HWN,
        (size_t)CC * CC, (size_t)C3 * HWN, (size_t)CC * HWN);
}